// round 17
// baseline (speedup 1.0000x reference)
#include <cuda_runtime.h>
#include <cstdint>

// ============================================================================
// KLinear: y = x @ W + bias,  W = (kron(L0,R0)+kron(L1,R1)+kron(L2,R2))/3
// Factorized two-stage GEMMs on mma.sync m16n8k8 tf32 (base ISA).
//   GEMM1: T[(m,a), d] = sum_c x[m, a*C+c] * R[c,d]
//   GEMM2: y[m][b*D+d] += sum_a (L[a,b]/3) * T[(m,a), d]
// R17: 128 threads / 4 warps, warp blocks 4x4 tiles (1.5 LDS/mma vs 2.0) in
// both GEMMs (2x8 for GEMM2 when B=32). Same smem layout/fragment maps as
// R16 (proven), generalized block shape. 2 CTAs/SM; regs uncapped (smem-bound).
// ============================================================================

static constexpr int THREADS = 128;
static constexpr int MT = 2;
static constexpr int NF = 4096;

// SMEM layout (float indices) — identical to R16
static constexpr int YS    = 4352;     // 4096 + 2*(4096/32)
static constexpr int OFF_Y = 0;        // 2*4352 = 8704
static constexpr int OFF_T = 8704;     // max MT*A*DP = 256*40 = 10240
static constexpr int OFF_X = 18944;    // x chunk / L staging (aliased), 5120
static constexpr int OFF_R = 24064;    // 16*136 max = 2176
static constexpr int SMEM_FLOATS = 26240;
static constexpr int SMEM_BYTES  = SMEM_FLOATS * 4;   // 104960

__device__ __forceinline__ uint32_t f2tf(float f) {
    uint32_t r; asm("cvt.rna.tf32.f32 %0, %1;" : "=r"(r) : "f"(f)); return r;
}

__device__ __forceinline__ void mma8(float* c, const uint32_t* a, const uint32_t* b) {
    asm volatile(
        "mma.sync.aligned.m16n8k8.row.col.f32.tf32.tf32.f32 "
        "{%0,%1,%2,%3}, {%4,%5,%6,%7}, {%8,%9}, {%0,%1,%2,%3};"
        : "+f"(c[0]), "+f"(c[1]), "+f"(c[2]), "+f"(c[3])
        : "r"(a[0]), "r"(a[1]), "r"(a[2]), "r"(a[3]), "r"(b[0]), "r"(b[1]));
}

template<int A, int B, int C, int D>
__device__ __forceinline__ void factor(
    const float* __restrict__ x, const float* __restrict__ Lg,
    const float* __restrict__ Rg, float* __restrict__ smem, int m0, int tid)
{
    constexpr int DP  = D + 8;      // padded row stride (R, T)
    constexpr int XS  = 20;         // x chunk row stride (16 + 4)
    constexpr int BS  = B + 8;      // native L row stride (BS % 32 == 8)
    constexpr int NC1 = C / 16;     // K chunks, stage 1
    constexpr int NC2 = A / 32;     // K chunks, stage 2
    // GEMM1: (2A/16)x(D/8) tiles, 4x4 blocks -> grid (A/32)x(D/32) = 4 warps
    constexpr int GC1 = D / 32;
    // GEMM2 per m (2 warps): blocks RB2 x CB2, RB2*CB2 = 16 tiles
    constexpr int RB2 = (B >= 64) ? 4 : 2;
    constexpr int CB2 = 16 / RB2;
    constexpr int GC2 = (D / 8) / CB2;       // grid cols; grid rows x cols = 2
    constexpr int XN  = (MT * A * 4) / THREADS;   // 4 / 2 / 8 (exact)
    constexpr int RN  = (4 * D) / THREADS;        // 2 / 4 / 1 (exact)
    constexpr int LN  = (8 * B) / THREADS;        // 4 / 2 / 8 (exact)

    float*    ys   = smem + OFF_Y;
    uint32_t* ts   = (uint32_t*)(smem + OFF_T);
    uint32_t* xs   = (uint32_t*)(smem + OFF_X);
    uint32_t* rs   = (uint32_t*)(smem + OFF_R);
    uint32_t* lnat = (uint32_t*)(smem + OFF_X);   // alias (x chunk dead in GEMM2)

    const int w    = tid >> 5;
    const int lane = tid & 31;
    const int gid  = lane >> 2;
    const int tig  = lane & 3;

    // ---- register-staged chunk prefetch (GEMM1) ----
    float4 xpf[XN];
    float4 rpf[RN];
    auto ldg_chunk = [&](int ck) {
        #pragma unroll
        for (int u = 0; u < XN; u++) {
            int s = tid + u * THREADS;
            int r = s >> 2, c4 = s & 3;
            int m = r / A, a = r % A;
            xpf[u] = *(const float4*)&x[(size_t)(m0 + m) * NF + a * C + ck * 16 + c4 * 4];
        }
        #pragma unroll
        for (int u = 0; u < RN; u++) {
            int s = tid + u * THREADS;
            int k = s / (D / 4), d4 = s % (D / 4);
            rpf[u] = *(const float4*)&Rg[(ck * 16 + k) * D + d4 * 4];
        }
    };
    auto sts_chunk = [&]() {
        #pragma unroll
        for (int u = 0; u < XN; u++) {
            int s = tid + u * THREADS;
            int r = s >> 2, c4 = s & 3;
            uint4 q = make_uint4(f2tf(xpf[u].x), f2tf(xpf[u].y),
                                 f2tf(xpf[u].z), f2tf(xpf[u].w));
            *(uint4*)&xs[r * XS + c4 * 4] = q;
        }
        #pragma unroll
        for (int u = 0; u < RN; u++) {
            int s = tid + u * THREADS;
            int k = s / (D / 4), d4 = s % (D / 4);
            uint4 q = make_uint4(f2tf(rpf[u].x), f2tf(rpf[u].y),
                                 f2tf(rpf[u].z), f2tf(rpf[u].w));
            *(uint4*)&rs[k * DP + d4 * 4] = q;
        }
    };

    // ================= GEMM1 (4x4 warp blocks) =================
    const int wr1 = w / GC1, wc1 = w % GC1;
    float accT[16][4];
    #pragma unroll
    for (int t = 0; t < 16; t++)
        #pragma unroll
        for (int q = 0; q < 4; q++) accT[t][q] = 0.0f;

    ldg_chunk(0);   // global reads only — safe before the barrier
    for (int ck = 0; ck < NC1; ck++) {
        __syncthreads();           // buffers free (prev consume / prev factor done)
        sts_chunk();               // store chunk ck
        if (ck + 1 < NC1) ldg_chunk(ck + 1);   // prefetch overlaps consume
        __syncthreads();           // chunk ck visible

        #pragma unroll
        for (int kt = 0; kt < 2; kt++) {
            uint32_t af[4][4], bf[4][2];
            #pragma unroll
            for (int i = 0; i < 4; i++) {
                int r0 = (wr1 * 4 + i) * 16 + gid;
                af[i][0] = xs[r0 * XS + kt * 8 + tig];
                af[i][1] = xs[(r0 + 8) * XS + kt * 8 + tig];
                af[i][2] = xs[r0 * XS + kt * 8 + tig + 4];
                af[i][3] = xs[(r0 + 8) * XS + kt * 8 + tig + 4];
            }
            #pragma unroll
            for (int j = 0; j < 4; j++) {
                int nc = (wc1 * 4 + j) * 8 + gid;
                bf[j][0] = rs[(kt * 8 + tig) * DP + nc];
                bf[j][1] = rs[(kt * 8 + tig + 4) * DP + nc];
            }
            #pragma unroll
            for (int i = 0; i < 4; i++)
                #pragma unroll
                for (int j = 0; j < 4; j++)
                    mma8(accT[i * 4 + j], af[i], bf[j]);
        }
    }

    // ---- store T (tf32): rows (m,a), cols d ----
    __syncthreads();
    #pragma unroll
    for (int i = 0; i < 4; i++)
        #pragma unroll
        for (int j = 0; j < 4; j++) {
            int r0 = (wr1 * 4 + i) * 16 + gid;
            int nc = (wc1 * 4 + j) * 8 + 2 * tig;
            uint2 lo = make_uint2(f2tf(accT[i * 4 + j][0]), f2tf(accT[i * 4 + j][1]));
            uint2 hi = make_uint2(f2tf(accT[i * 4 + j][2]), f2tf(accT[i * 4 + j][3]));
            *(uint2*)&ts[r0 * DP + nc]       = lo;
            *(uint2*)&ts[(r0 + 8) * DP + nc] = hi;
        }
    __syncthreads();   // T visible; x chunk (lnat alias) free to overwrite

    // ================= GEMM2 (RB2 x CB2 warp blocks) =================
    const int m   = w >> 1;           // 2 warps per m-row
    const int sw  = w & 1;
    const int wr2 = sw / GC2, wc2 = sw % GC2;
    float accY[16][4];
    #pragma unroll
    for (int t = 0; t < 16; t++)
        #pragma unroll
        for (int q = 0; q < 4; q++) accY[t][q] = 0.0f;

    for (int ac = 0; ac < NC2; ac++) {
        if (ac) __syncthreads();   // protect lnat overwrite vs previous mma reads
        // ---- L chunk in NATIVE layout: lnat[a][b] = L[ac*32+a][b]/3, tf32 ----
        #pragma unroll
        for (int u = 0; u < LN; u++) {
            int s = tid + u * THREADS;
            int a = s / (B / 4), b4 = s % (B / 4);
            float4 v = *(const float4*)&Lg[(ac * 32 + a) * B + b4 * 4];
            uint4 q = make_uint4(f2tf(v.x * (1.0f / 3.0f)),
                                 f2tf(v.y * (1.0f / 3.0f)),
                                 f2tf(v.z * (1.0f / 3.0f)),
                                 f2tf(v.w * (1.0f / 3.0f)));
            *(uint4*)&lnat[a * BS + b4 * 4] = q;
        }
        __syncthreads();

        #pragma unroll
        for (int kt = 0; kt < 4; kt++) {
            uint32_t af[RB2][4], bf[CB2][2];
            #pragma unroll
            for (int i = 0; i < RB2; i++) {
                int rbase = (wr2 * RB2 + i) * 16 + gid;   // b index
                int c0 = kt * 8 + tig;                    // a index (lo)
                af[i][0] = lnat[c0 * BS + rbase];
                af[i][1] = lnat[c0 * BS + rbase + 8];
                af[i][2] = lnat[(c0 + 4) * BS + rbase];
                af[i][3] = lnat[(c0 + 4) * BS + rbase + 8];
            }
            #pragma unroll
            for (int j = 0; j < CB2; j++) {
                int nc = (wc2 * CB2 + j) * 8 + gid;       // d index
                bf[j][0] = ts[(m * A + ac * 32 + kt * 8 + tig) * DP + nc];
                bf[j][1] = ts[(m * A + ac * 32 + kt * 8 + tig + 4) * DP + nc];
            }
            #pragma unroll
            for (int i = 0; i < RB2; i++)
                #pragma unroll
                for (int j = 0; j < CB2; j++)
                    mma8(accY[i * CB2 + j], af[i], bf[j]);
        }
    }

    // ---- RMW y (swizzled): per-thread disjoint within a factor ----
    #pragma unroll
    for (int i = 0; i < RB2; i++)
        #pragma unroll
        for (int j = 0; j < CB2; j++) {
            int b = (wr2 * RB2 + i) * 16 + gid;
            int d = (wc2 * CB2 + j) * 8 + 2 * tig;
            int n0 = b * D + d;
            int s0 = n0 + 2 * (n0 >> 5);
            float2 v0 = *(float2*)&ys[m * YS + s0];
            v0.x += accY[i * CB2 + j][0]; v0.y += accY[i * CB2 + j][1];
            *(float2*)&ys[m * YS + s0] = v0;
            int n2 = (b + 8) * D + d;
            int s2 = n2 + 2 * (n2 >> 5);
            float2 v2 = *(float2*)&ys[m * YS + s2];
            v2.x += accY[i * CB2 + j][2]; v2.y += accY[i * CB2 + j][3];
            *(float2*)&ys[m * YS + s2] = v2;
        }
}

__global__ __launch_bounds__(THREADS, 2) void klinear_kernel(
    const float* __restrict__ x,
    const float* __restrict__ L0, const float* __restrict__ R0,
    const float* __restrict__ L1, const float* __restrict__ R1,
    const float* __restrict__ L2, const float* __restrict__ R2,
    const float* __restrict__ bias,
    float* __restrict__ out)
{
    extern __shared__ float smem[];
    const int tid = threadIdx.x;
    const int m0  = blockIdx.x * MT;

    // zero y accumulator (bias added in epilogue)
    for (int i = tid; i < MT * YS; i += THREADS)
        smem[OFF_Y + i] = 0.0f;
    // (first factor's chunk-top __syncthreads orders this before any use)

    factor< 64,  64,  64,  64>(x, L0, R0, smem, m0, tid);
    factor< 32,  32, 128, 128>(x, L1, R1, smem, m0, tid);
    factor<128, 128,  32,  32>(x, L2, R2, smem, m0, tid);

    __syncthreads();

    // epilogue: y + bias -> out; thread owns n in [32*tid, 32*tid+32)
    const int n0 = tid * 32;
    #pragma unroll
    for (int h = 0; h < 4; h++) {
        int nb = n0 + h * 8;
        int s  = nb + 2 * (nb >> 5);   // constant shift within each 8-run
        float4 b0 = *(const float4*)&bias[nb];
        float4 b1 = *(const float4*)&bias[nb + 4];
        #pragma unroll
        for (int m = 0; m < MT; m++) {
            const float* yr = smem + OFF_Y + m * YS + s;
            float2 p0 = *(const float2*)&yr[0];
            float2 p1 = *(const float2*)&yr[2];
            float2 p2 = *(const float2*)&yr[4];
            float2 p3 = *(const float2*)&yr[6];
            float4 o0 = make_float4(p0.x + b0.x, p0.y + b0.y, p1.x + b0.z, p1.y + b0.w);
            float4 o1 = make_float4(p2.x + b1.x, p2.y + b1.y, p3.x + b1.z, p3.y + b1.w);
            *(float4*)&out[(size_t)(m0 + m) * NF + nb]     = o0;
            *(float4*)&out[(size_t)(m0 + m) * NF + nb + 4] = o1;
        }
    }
}

extern "C" void kernel_launch(void* const* d_in, const int* in_sizes, int n_in,
                              void* d_out, int out_size)
{
    const float* x    = (const float*)d_in[0];
    const float* L0   = (const float*)d_in[1];
    const float* R0   = (const float*)d_in[2];
    const float* L1   = (const float*)d_in[3];
    const float* R1   = (const float*)d_in[4];
    const float* L2   = (const float*)d_in[5];
    const float* R2   = (const float*)d_in[6];
    const float* bias = (const float*)d_in[7];
    float* out = (float*)d_out;

    static bool attr_set = false;
    if (!attr_set) {
        cudaFuncSetAttribute(klinear_kernel,
                             cudaFuncAttributeMaxDynamicSharedMemorySize, SMEM_BYTES);
        attr_set = true;
    }

    klinear_kernel<<<16384 / MT, THREADS, SMEM_BYTES>>>(
        x, L0, R0, L1, R1, L2, R2, bias, out);
}